// round 14
// baseline (speedup 1.0000x reference)
#include <cuda_runtime.h>
#include <math.h>
#include <math_constants.h>

#ifndef CUDART_INF_F
#define CUDART_INF_F __int_as_float(0x7f800000)
#endif

// ---------------------------------------------------------------------------
// AdaptivePrecisionKVCache — R13: 3-kernel structure + 256-bit LDG/STG.
//   small bin: |x| <= 0.01, levels = 15 ; large bin: |x| > 0.01, levels = 255
//   valid bin <=> bmin < bmax
// R13 delta vs R12 (66.0us):
//   - ld.global.nc.v8.f32 / st.global.cs.v8.f32 (Blackwell 256-bit LDG/STG)
//     in both streaming kernels: halves LSU issue slots per byte; both kernels
//     were issue/alu co-limited (issue 42%, alu 51% in reduce).
// ---------------------------------------------------------------------------

#define THRESH 0.01f
#define RED_BLOCKS 2368          // 148 SMs * 16
#define RED_THREADS 256
#define DQ_THREADS 256
#define DQ_UNROLL 2              // 2 x v8 = 16 floats/thread

__device__ float4 g_partials[RED_BLOCKS];  // x=smin, y=smax, z=lmin, w=lmax
__device__ float4 g_ps;                    // smin, 15/sden, sden/15, svalid
__device__ float4 g_pl;                    // lmin, 255/lden, lden/255, lvalid

struct MM { float smin, smax, lmin, lmax; };

__device__ __forceinline__ void mm_init(MM& m) {
    float inf = CUDART_INF_F;
    m.smin = inf; m.smax = -inf; m.lmin = inf; m.lmax = -inf;
}

// R3-proven branchless form: FSETP + 4 FSEL + 4 FMNMX (measured best).
__device__ __forceinline__ void acc_val(float x, MM& m) {
    bool big = fabsf(x) > THRESH;
    float inf = CUDART_INF_F;
    m.smin = fminf(m.smin, big ?  inf : x);
    m.smax = fmaxf(m.smax, big ? -inf : x);
    m.lmin = fminf(m.lmin, big ? x :  inf);
    m.lmax = fmaxf(m.lmax, big ? x : -inf);
}

__device__ __forceinline__ void mm_merge(MM& a, const MM& b) {
    a.smin = fminf(a.smin, b.smin);
    a.smax = fmaxf(a.smax, b.smax);
    a.lmin = fminf(a.lmin, b.lmin);
    a.lmax = fmaxf(a.lmax, b.lmax);
}

__device__ __forceinline__ void warp_reduce(MM& m) {
    #pragma unroll
    for (int o = 16; o > 0; o >>= 1) {
        m.smin = fminf(m.smin, __shfl_xor_sync(0xffffffffu, m.smin, o));
        m.smax = fmaxf(m.smax, __shfl_xor_sync(0xffffffffu, m.smax, o));
        m.lmin = fminf(m.lmin, __shfl_xor_sync(0xffffffffu, m.lmin, o));
        m.lmax = fmaxf(m.lmax, __shfl_xor_sync(0xffffffffu, m.lmax, o));
    }
}

__device__ __forceinline__ MM block_reduce(MM m) {
    warp_reduce(m);
    __shared__ MM sm[RED_THREADS / 32];
    int w = threadIdx.x >> 5;
    if ((threadIdx.x & 31) == 0) sm[w] = m;
    __syncthreads();
    MM r = sm[0];
    if (threadIdx.x == 0) {
        #pragma unroll
        for (int i = 1; i < RED_THREADS / 32; i++) mm_merge(r, sm[i]);
    }
    return r;
}

// ---- 256-bit memory ops (Blackwell LDG.256 / STG.256) ----
__device__ __forceinline__ void ld256(const float* p, float* v) {
    asm("ld.global.nc.v8.f32 {%0,%1,%2,%3,%4,%5,%6,%7}, [%8];"
        : "=f"(v[0]), "=f"(v[1]), "=f"(v[2]), "=f"(v[3]),
          "=f"(v[4]), "=f"(v[5]), "=f"(v[6]), "=f"(v[7])
        : "l"(p));
}

__device__ __forceinline__ void st256cs(float* p, const float* v) {
    asm volatile("st.global.cs.v8.f32 [%0], {%1,%2,%3,%4,%5,%6,%7,%8};"
        :: "l"(p),
           "f"(v[0]), "f"(v[1]), "f"(v[2]), "f"(v[3]),
           "f"(v[4]), "f"(v[5]), "f"(v[6]), "f"(v[7])
        : "memory");
}

__device__ __forceinline__ void acc_vec8(const float* v, MM& m) {
    #pragma unroll
    for (int k = 0; k < 8; k++) acc_val(v[k], m);
}

__global__ void __launch_bounds__(RED_THREADS)
k_reduce(const float* __restrict__ in, int n) {
    MM m0, m1, m2, m3;
    mm_init(m0); mm_init(m1); mm_init(m2); mm_init(m3);
    int nv8 = n >> 3;
    int S = gridDim.x * blockDim.x;
    int tid = blockIdx.x * blockDim.x + threadIdx.x;
    int i = tid;
    for (; i + 3 * S < nv8; i += 4 * S) {
        float v0[8], v1[8], v2[8], v3[8];
        ld256(in + ((long)i) * 8,            v0);
        ld256(in + ((long)(i + S)) * 8,      v1);
        ld256(in + ((long)(i + 2 * S)) * 8,  v2);
        ld256(in + ((long)(i + 3 * S)) * 8,  v3);
        acc_vec8(v0, m0); acc_vec8(v1, m1); acc_vec8(v2, m2); acc_vec8(v3, m3);
    }
    for (; i < nv8; i += S) {
        float v[8];
        ld256(in + ((long)i) * 8, v);
        acc_vec8(v, m0);
    }
    // scalar tail (n not multiple of 8)
    if (blockIdx.x == 0) {
        for (int j = (nv8 << 3) + threadIdx.x; j < n; j += blockDim.x)
            acc_val(in[j], m0);
    }
    mm_merge(m0, m1); mm_merge(m2, m3); mm_merge(m0, m2);
    MM r = block_reduce(m0);
    if (threadIdx.x == 0)
        g_partials[blockIdx.x] = make_float4(r.smin, r.smax, r.lmin, r.lmax);
}

__global__ void __launch_bounds__(RED_THREADS)
k_finalize() {
    MM m; mm_init(m);
    for (int i = threadIdx.x; i < RED_BLOCKS; i += blockDim.x) {
        float4 p = g_partials[i];
        m.smin = fminf(m.smin, p.x);
        m.smax = fmaxf(m.smax, p.y);
        m.lmin = fminf(m.lmin, p.z);
        m.lmax = fmaxf(m.lmax, p.w);
    }
    MM f = block_reduce(m);
    if (threadIdx.x == 0) {
        bool sv = f.smin < f.smax;
        float sd = sv ? (f.smax - f.smin) : 1.0f;
        g_ps = make_float4(f.smin, 15.0f / sd, sd / 15.0f, sv ? 1.0f : 0.0f);
        bool lv = f.lmin < f.lmax;
        float ld = lv ? (f.lmax - f.lmin) : 1.0f;
        g_pl = make_float4(f.lmin, 255.0f / ld, ld / 255.0f, lv ? 1.0f : 0.0f);
    }
}

__device__ __forceinline__ float dq(float x, float4 ps, float4 pl) {
    bool big = fabsf(x) > THRESH;
    float bmin = big ? pl.x : ps.x;
    float sc   = big ? pl.y : ps.y;
    float iv   = big ? pl.z : ps.z;
    float vd   = big ? pl.w : ps.w;
    float q = rintf((x - bmin) * sc);   // rintf == round-half-even == jnp.round
    float d = fmaf(q, iv, bmin);
    return (vd != 0.0f) ? d : x;
}

// Reversed block order (start on the L2-hot tail) + 256-bit evict-first stores.
__global__ void __launch_bounds__(DQ_THREADS)
k_dequant(const float* __restrict__ in, float* __restrict__ out, int n) {
    const float4 ps = g_ps;
    const float4 pl = g_pl;
    int nv8 = n >> 3;
    int rb = gridDim.x - 1 - blockIdx.x;
    int base = rb * (DQ_UNROLL * DQ_THREADS) + threadIdx.x;

    int idx[DQ_UNROLL];
    float v[DQ_UNROLL][8];
    bool ok[DQ_UNROLL];
    #pragma unroll
    for (int u = 0; u < DQ_UNROLL; u++) {
        idx[u] = base + u * DQ_THREADS;
        ok[u] = idx[u] < nv8;
        if (ok[u]) ld256(in + ((long)idx[u]) * 8, v[u]);
    }
    #pragma unroll
    for (int u = 0; u < DQ_UNROLL; u++) {
        if (ok[u]) {
            #pragma unroll
            for (int k = 0; k < 8; k++) v[u][k] = dq(v[u][k], ps, pl);
            st256cs(out + ((long)idx[u]) * 8, v[u]);
        }
    }
    // scalar tail (n not multiple of 8)
    if (blockIdx.x == 0) {
        for (int j = (nv8 << 3) + threadIdx.x; j < n; j += blockDim.x)
            __stcs(&out[j], dq(in[j], ps, pl));
    }
}

extern "C" void kernel_launch(void* const* d_in, const int* in_sizes, int n_in,
                              void* d_out, int out_size) {
    (void)n_in; (void)out_size;
    const float* in = (const float*)d_in[0];
    float* out = (float*)d_out;
    int n = in_sizes[0];

    int nv8 = n >> 3;

    k_reduce<<<RED_BLOCKS, RED_THREADS>>>(in, n);
    k_finalize<<<1, RED_THREADS>>>();

    int chunk = DQ_UNROLL * DQ_THREADS;
    int dq_blocks = (nv8 + chunk - 1) / chunk;
    if (dq_blocks < 1) dq_blocks = 1;
    k_dequant<<<dq_blocks, DQ_THREADS>>>(in, out, n);
}